// round 11
// baseline (speedup 1.0000x reference)
#include <cuda_runtime.h>
#include <math.h>

#define NTOK 32768
#define CFEAT 64
#define NBLK 16           // persistent grid for attn stack (all resident)

// ---------------- scratch (static device memory; no allocation) ----------------
__device__ float g_t  [NTOK * CFEAT];   // tokens [n][c]
__device__ float g_hT [NTOK * CFEAT];   // channel-major [c][n]
__device__ float g_qs [NTOK * CFEAT];
__device__ float g_ks [NTOK * CFEAT];
__device__ float g_vs [NTOK * CFEAT];
__device__ int   g_idx3[3 * NTOK];
__device__ int   g_M3[3];
__device__ unsigned g_gen = 0;          // barrier generation
__device__ unsigned g_arrive = 0;       // arrival count (self-restoring)

// ---------------- software grid barrier (all NBLK blocks resident) -------------
__device__ __forceinline__ void grid_bar()
{
    __syncthreads();
    if (threadIdx.x == 0) {
        __threadfence();
        unsigned gen = *(volatile unsigned*)&g_gen;
        if (atomicAdd(&g_arrive, 1u) == NBLK - 1) {
            g_arrive = 0;
            __threadfence();
            atomicAdd(&g_gen, 1u);
        } else {
            while (*(volatile unsigned*)&g_gen == gen) {}
        }
        __threadfence();
    }
    __syncthreads();
}

// ---------------- dilation index build (ss-table, bit-exact vs numpy) ----------
__global__ void __launch_bounds__(256) build_idx_kernel()
{
    __shared__ unsigned char valid[769];
    __shared__ int scan[256];
    int bi  = blockIdx.x;
    int dil = (bi == 0) ? 2 : (bi == 1) ? 4 : 6;
    int* out = g_idx3 + bi * NTOK;
    int tid  = threadIdx.x;
    float fd = (float)dil;

    for (int ss = tid; ss < 769; ss += 256) {
        float d = sqrtf((float)ss);
        valid[ss] = ((fmodf(d, fd) == 0.0f) || (ss == 0)) ? 1 : 0;
    }
    __syncthreads();

    int base = tid * 128;
    unsigned long long fl0 = 0ull, fl1 = 0ull;
    int ccnt = 0;
    for (int j = 0; j < 128; ++j) {
        int n = base + j;
        int zz = (n >> 10) - 16, yy = ((n >> 5) & 31) - 16, xx = (n & 31) - 16;
        int ss = zz*zz + yy*yy + xx*xx;
        if (valid[ss]) {
            if (j < 64) fl0 |= (1ull << j); else fl1 |= (1ull << (j - 64));
            ccnt++;
        }
    }
    scan[tid] = ccnt;
    __syncthreads();
    for (int off = 1; off < 256; off <<= 1) {
        int v = (tid >= off) ? scan[tid - off] : 0;
        __syncthreads();
        scan[tid] += v;
        __syncthreads();
    }
    int pos = scan[tid] - ccnt;
    for (int j = 0; j < 64; ++j)
        if (fl0 & (1ull << j)) out[pos++] = base + j;
    for (int j = 0; j < 64; ++j)
        if (fl1 & (1ull << j)) out[pos++] = base + 64 + j;
    if (tid == 255) g_M3[bi] = scan[255];
}

// ---------------- fused patch conv + pos embed, dual-layout write --------------
__global__ void __launch_bounds__(256) conv_pos_kernel(
    const float* __restrict__ x,
    const float* __restrict__ W,    // [64][64]
    const float* __restrict__ b,
    const float* __restrict__ pos)  // [64][32768]
{
    __shared__ float S[128 * 68];     // phase1: Praw[64][128]; phase2: O[128][68]
    int bid = blockIdx.x;
    int z   = bid >> 3, yq = bid & 7;
    int y0  = yq * 4;
    int n0  = z * 1024 + y0 * 32;     // 128 contiguous tokens
    int tid = threadIdx.x;

    #pragma unroll
    for (int j = 0; j < 8; ++j) {
        int e   = tid + 256 * j;
        int r   = e >> 5;             // 0..63: dz = r>>4, yloc = r&15
        int c4  = e & 31;
        const float4* src = (const float4*)(x
            + (size_t)(4*z + (r >> 4)) * 16384
            + (4*y0 + (r & 15)) * 128 + c4 * 4);
        *(float4*)&S[r * 128 + c4 * 4] = *src;
    }
    __syncthreads();

    int ch = tid & 63;
    int tg = tid >> 6;                // y row 0..3
    float w[64];
    {
        const float4* wp = (const float4*)(W + ch * 64);
        #pragma unroll
        for (int i = 0; i < 16; ++i) {
            float4 t4 = wp[i];
            w[4*i] = t4.x; w[4*i+1] = t4.y; w[4*i+2] = t4.z; w[4*i+3] = t4.w;
        }
    }
    float bv = b[ch];
    float acc[32];
    #pragma unroll
    for (int i = 0; i < 32; ++i) acc[i] = bv;

    #pragma unroll
    for (int k4 = 0; k4 < 16; ++k4) {         // k4 = dz*4+dy
        int row = (k4 >> 2) * 16 + tg * 4 + (k4 & 3);
        const float4* Pr = (const float4*)&S[row * 128];
        float wx = w[4*k4], wy = w[4*k4+1], wz2 = w[4*k4+2], ww = w[4*k4+3];
        #pragma unroll
        for (int i = 0; i < 32; ++i) {
            float4 p = Pr[i];
            acc[i] += p.x * wx;
            acc[i] += p.y * wy;
            acc[i] += p.z * wz2;
            acc[i] += p.w * ww;
        }
    }
    __syncthreads();

    #pragma unroll
    for (int i = 0; i < 32; ++i)
        S[(tg * 32 + i) * 68 + ch] = acc[i];
    __syncthreads();

    #pragma unroll
    for (int rep = 0; rep < 32; ++rep) {
        int e  = tid + 256 * rep;
        int cc = e >> 7, t = e & 127;
        float v = S[t * 68 + cc] + pos[cc * NTOK + n0 + t];
        S[t * 68 + cc] = v;
        g_hT[cc * NTOK + n0 + t] = v;
    }
    __syncthreads();

    #pragma unroll
    for (int j = 0; j < 8; ++j) {
        int e  = tid + 256 * j;
        int t  = e >> 4, c4 = e & 15;
        float4 v = *(const float4*)&S[t * 68 + c4 * 4];
        *(float4*)&g_t[(size_t)(n0 + t) * 64 + c4 * 4] = v;
    }
}

// =================== persistent fused attention stack ==========================
// grid = NBLK x 512. Per dilation: QKV | bar | flash (+proj/resid/scatter) | bar.
// Flash lane layout: 32 queries x 16 lanes; lane = (kg keys, cg channel-quarter)
// -> max per-thread array is 16 floats (no register spills).
__global__ void __launch_bounds__(512) fused_attn_kernel(
    const float* __restrict__ qkvw0, const float* __restrict__ qkvb0,
    const float* __restrict__ pw0,   const float* __restrict__ pb0,
    const float* __restrict__ qkvw1, const float* __restrict__ qkvb1,
    const float* __restrict__ pw1,   const float* __restrict__ pb1,
    const float* __restrict__ qkvw2, const float* __restrict__ qkvb2,
    const float* __restrict__ pw2,   const float* __restrict__ pb2)
{
    __shared__ float SM[160 * 68];            // 43.5 KB, re-aliased per stage

    int tid = threadIdx.x;
    int bid = blockIdx.x;

    const float* QW[3] = {qkvw0, qkvw1, qkvw2};
    const float* QB[3] = {qkvb0, qkvb1, qkvb2};
    const float* PW[3] = {pw0, pw1, pw2};
    const float* PB[3] = {pb0, pb1, pb2};

    for (int di = 0; di < 3; ++di) {
        int M = g_M3[di];
        const int* __restrict__ idx = g_idx3 + di * NTOK;
        int mtiles = (M + 31) >> 5;

        // ---------------- stage: QKV (scale 1/8 folded into Q) -----------------
        {
            float (*Ts)[68] = (float(*)[68])SM;
            const float* W  = QW[di];
            const float* bb = QB[di];

            int oc   = tid >> 1;          // 0..255 (valid < 192)
            int half = tid & 1;
            float w[64]; float bv = 0.f;
            if (oc < 192) {
                const float4* wr = (const float4*)(W + oc * 64);
                #pragma unroll
                for (int i = 0; i < 16; ++i) {
                    float4 t4 = wr[i];
                    w[4*i] = t4.x; w[4*i+1] = t4.y; w[4*i+2] = t4.z; w[4*i+3] = t4.w;
                }
                bv = bb[oc];
            }

            for (int mt = bid; mt < mtiles; mt += NBLK) {
                int m0 = mt * 32;
                __syncthreads();
                #pragma unroll
                for (int j = 0; j < 4; ++j) {
                    int e = tid + 512 * j;
                    int ml = e >> 6, k = e & 63;
                    int m = m0 + ml;
                    Ts[ml][k] = (m < M) ? g_t[idx[m] * 64 + k] : 0.f;
                }
                __syncthreads();
                if (oc < 192) {
                    int mmax = min(32, M - m0);
                    #pragma unroll
                    for (int g = 0; g < 2; ++g) {
                        int ml0 = half * 16 + g * 8;
                        float acc[8];
                        #pragma unroll
                        for (int u = 0; u < 8; ++u) acc[u] = bv;
                        #pragma unroll
                        for (int k4 = 0; k4 < 16; ++k4) {
                            #pragma unroll
                            for (int u = 0; u < 8; ++u) {
                                float4 t4 = *(const float4*)&Ts[ml0 + u][k4 * 4];
                                acc[u] += t4.x * w[4*k4];
                                acc[u] += t4.y * w[4*k4+1];
                                acc[u] += t4.z * w[4*k4+2];
                                acc[u] += t4.w * w[4*k4+3];
                            }
                        }
                        #pragma unroll
                        for (int u = 0; u < 8; ++u) {
                            int ml = ml0 + u;
                            if (ml < mmax) {
                                int m = m0 + ml;
                                if      (oc <  64) g_qs[m * 64 + oc]       = acc[u] * 0.125f;
                                else if (oc < 128) g_ks[m * 64 + oc - 64]  = acc[u];
                                else               g_vs[m * 64 + oc - 128] = acc[u];
                            }
                        }
                    }
                }
            }
        }
        grid_bar();

        // ---------- stage: flash attn + proj + resid + scatter (spill-free) ----
        {
            float (*Ksm)[68] = (float(*)[68])SM;
            float (*Vsm)[68] = (float(*)[68])(SM + 64 * 68);
            float (*Ysm)[68] = (float(*)[68])(SM + 128 * 68);  // 32 rows
            float (*Wsm)[68] = (float(*)[68])(SM + 64 * 68);   // alias Vsm post-flash

            int r  = tid >> 4;        // query row 0..31
            int qq = tid & 15;
            int kg = qq >> 2;         // key group: keys nl = 4*j + kg
            int cg = qq & 3;          // channel quarter: [cg*16, cg*16+16)

            for (int mt = bid; mt < mtiles; mt += NBLK) {
                int  m0    = mt * 32;
                int  m     = m0 + r;
                bool valid = (m < M);

                float qreg[16];
                {
                    const float4* qp = (const float4*)
                        (g_qs + (size_t)(valid ? m : m0) * 64 + cg * 16);
                    #pragma unroll
                    for (int i = 0; i < 4; ++i) {
                        float4 v = qp[i];
                        qreg[4*i] = v.x; qreg[4*i+1] = v.y;
                        qreg[4*i+2] = v.z; qreg[4*i+3] = v.w;
                    }
                }
                float y[16];
                #pragma unroll
                for (int i = 0; i < 16; ++i) y[i] = 0.f;
                float row_max = -1e30f, row_sum = 0.f;

                for (int n0 = 0; n0 < M; n0 += 64) {
                    __syncthreads();
                    #pragma unroll
                    for (int j = 0; j < 2; ++j) {
                        int e = tid + 512 * j;
                        int nl = e >> 4, k4 = e & 15;
                        int n = n0 + nl;
                        float4 kv = make_float4(0.f, 0.f, 0.f, 0.f);
                        float4 vv = kv;
                        if (n < M) {
                            kv = *(const float4*)(g_ks + n * 64 + k4 * 4);
                            vv = *(const float4*)(g_vs + n * 64 + k4 * 4);
                        }
                        *(float4*)&Ksm[nl][k4 * 4] = kv;
                        *(float4*)&Vsm[nl][k4 * 4] = vv;
                    }
                    __syncthreads();

                    // scores: partial over 16 channels, reduce across cg lanes
                    float p[16];
                    float tmax = -1e30f;
                    #pragma unroll
                    for (int j = 0; j < 16; ++j) {
                        int nl = 4 * j + kg;
                        float acc = 0.f;
                        #pragma unroll
                        for (int i = 0; i < 4; ++i) {
                            float4 kv = *(const float4*)&Ksm[nl][cg * 16 + 4 * i];
                            acc += qreg[4*i]   * kv.x;
                            acc += qreg[4*i+1] * kv.y;
                            acc += qreg[4*i+2] * kv.z;
                            acc += qreg[4*i+3] * kv.w;
                        }
                        acc += __shfl_xor_sync(0xffffffffu, acc, 1);
                        acc += __shfl_xor_sync(0xffffffffu, acc, 2);
                        if (n0 + nl >= M) acc = -1e30f;
                        p[j] = acc;
                        tmax = fmaxf(tmax, acc);
                    }
                    tmax = fmaxf(tmax, __shfl_xor_sync(0xffffffffu, tmax, 4));
                    tmax = fmaxf(tmax, __shfl_xor_sync(0xffffffffu, tmax, 8));

                    float nmax = fmaxf(row_max, tmax);
                    float corr = __expf(row_max - nmax);
                    float lsum = 0.f;
                    #pragma unroll
                    for (int j = 0; j < 16; ++j) {
                        p[j] = __expf(p[j] - nmax);
                        lsum += p[j];
                    }
                    lsum += __shfl_xor_sync(0xffffffffu, lsum, 4);
                    lsum += __shfl_xor_sync(0xffffffffu, lsum, 8);
                    row_sum = row_sum * corr + lsum;
                    row_max = nmax;
                    #pragma unroll
                    for (int i = 0; i < 16; ++i) y[i] *= corr;

                    // PV: own keys (kg), own channel quarter (cg)
                    #pragma unroll
                    for (int j = 0; j < 16; ++j) {
                        int nl = 4 * j + kg;
                        float pj = p[j];
                        #pragma unroll
                        for (int i = 0; i < 4; ++i) {
                            float4 v = *(const float4*)&Vsm[nl][cg * 16 + 4 * i];
                            y[4*i]   += pj * v.x;
                            y[4*i+1] += pj * v.y;
                            y[4*i+2] += pj * v.z;
                            y[4*i+3] += pj * v.w;
                        }
                    }
                }

                // reduce y over kg lanes (linear, commutes with rescales)
                #pragma unroll
                for (int i = 0; i < 16; ++i) {
                    y[i] += __shfl_xor_sync(0xffffffffu, y[i], 4);
                    y[i] += __shfl_xor_sync(0xffffffffu, y[i], 8);
                }
                float inv = 1.0f / row_sum;

                __syncthreads();              // flash reads of Ksm/Vsm done
                #pragma unroll
                for (int i = 0; i < 4; ++i)
                    *(float4*)&Ysm[r][cg * 16 + 4 * i] = make_float4(
                        y[4*i]*inv, y[4*i+1]*inv, y[4*i+2]*inv, y[4*i+3]*inv);

                // proj weights -> smem (alias Vsm region)
                #pragma unroll
                for (int j = 0; j < 2; ++j) {
                    int e = tid + 512 * j;    // 1024 float4
                    int row = e >> 4, c4 = e & 15;
                    *(float4*)&Wsm[row][c4 * 4] =
                        *(const float4*)(PW[di] + row * 64 + c4 * 4);
                }
                __syncthreads();

                // proj + residual + dual scatter
                int oc = tid & 63;
                int rb = tid >> 6;            // 0..7
                float bv = PB[di][oc];
                int mmax = min(32, M - m0);
                for (int rr = rb; rr < mmax; rr += 8) {
                    float a0 = bv;
                    #pragma unroll
                    for (int k4 = 0; k4 < 16; ++k4) {
                        float4 yv = *(const float4*)&Ysm[rr][k4 * 4];
                        float4 wv = *(const float4*)&Wsm[oc][k4 * 4];
                        a0 += yv.x * wv.x + yv.y * wv.y
                            + yv.z * wv.z + yv.w * wv.w;
                    }
                    a0 += Ysm[rr][oc];
                    int tok = idx[m0 + rr];
                    g_t [tok * 64 + oc]   = a0;
                    g_hT[oc * NTOK + tok] = a0;
                }
                __syncthreads();              // before next mtile reuses smem
            }
        }
        if (di < 2) grid_bar();
    }
}

// ---------------- trilinear x4 upsample: hT[c][32^3] -> out[c][128^3] ----------
__global__ void __launch_bounds__(256) upsample_kernel(float* __restrict__ out)
{
    const float S = 31.0f / 127.0f;
    int zo  = blockIdx.x;
    int c   = blockIdx.y;
    int tid = threadIdx.x;

    float pz = (float)zo * S;
    int z0 = (int)pz;
    int z1 = min(z0 + 1, 31);
    float wz = pz - (float)z0;

    __shared__ float F[1024];
    __shared__ float R[128][33];

    const float* p0 = g_hT + c * NTOK + z0 * 1024;
    const float* p1 = g_hT + c * NTOK + z1 * 1024;
    #pragma unroll
    for (int j = 0; j < 4; ++j) {
        int i = tid + 256 * j;
        float a = p0[i];
        F[i] = a + wz * (p1[i] - a);
    }
    __syncthreads();

    int w = tid >> 5, lane = tid & 31;

    #pragma unroll
    for (int j = 0; j < 16; ++j) {
        int yo = j * 8 + w;
        float py = (float)yo * S;
        int y0 = (int)py;
        int y1 = min(y0 + 1, 31);
        float wy = py - (float)y0;
        float a = F[y0 * 32 + lane];
        float b = F[y1 * 32 + lane];
        R[yo][lane] = a + wy * (b - a);
    }
    __syncthreads();

    int   x0[4], x1[4];
    float wx[4];
    #pragma unroll
    for (int j = 0; j < 4; ++j) {
        int xo = lane * 4 + j;
        float px = (float)xo * S;
        x0[j] = (int)px;
        x1[j] = min(x0[j] + 1, 31);
        wx[j] = px - (float)x0[j];
    }

    size_t obase = ((size_t)(c * 128 + zo)) * 16384;
    #pragma unroll
    for (int it = 0; it < 16; ++it) {
        int yo = it * 8 + w;
        const float* Rr = &R[yo][0];
        float4 o;
        #pragma unroll
        for (int j = 0; j < 4; ++j) {
            float r0 = Rr[x0[j]];
            (&o.x)[j] = r0 + wx[j] * (Rr[x1[j]] - r0);
        }
        __stcs((float4*)(out + obase + (size_t)yo * 128 + lane * 4), o);
    }
}

// ---------------- launch --------------------------------------------------------
extern "C" void kernel_launch(void* const* d_in, const int* in_sizes, int n_in,
                              void* d_out, int out_size)
{
    const float* x       = (const float*)d_in[0];
    const float* w_patch = (const float*)d_in[1];
    const float* b_patch = (const float*)d_in[2];
    const float* pos     = (const float*)d_in[3];

    build_idx_kernel<<<3, 256>>>();
    conv_pos_kernel<<<256, 256>>>(x, w_patch, b_patch, pos);

    fused_attn_kernel<<<NBLK, 512>>>(
        (const float*)d_in[4],  (const float*)d_in[5],
        (const float*)d_in[6],  (const float*)d_in[7],
        (const float*)d_in[8],  (const float*)d_in[9],
        (const float*)d_in[10], (const float*)d_in[11],
        (const float*)d_in[12], (const float*)d_in[13],
        (const float*)d_in[14], (const float*)d_in[15]);

    upsample_kernel<<<dim3(128, 64), 256>>>((float*)d_out);
}

// round 12
// speedup vs baseline: 1.1142x; 1.1142x over previous
#include <cuda_runtime.h>
#include <math.h>

#define NTOK 32768
#define NBLK 148                     // persistent grid: one block per SM
#define SMEM_FLOATS (320 * 68)       // 21760 floats = 87040 B (flash is max user)
#define SMEM_BYTES  (SMEM_FLOATS * 4)

// ---------------- scratch (static device memory; no allocation) ----------------
__device__ float g_t  [NTOK * 64];   // tokens [n][c]
__device__ float g_hT [NTOK * 64];   // channel-major [c][n]
__device__ float g_qs [NTOK * 64];
__device__ float g_ks [NTOK * 64];
__device__ float g_vs [NTOK * 64];
__device__ int   g_idx3[3 * NTOK];
__device__ int   g_M3[3];
__device__ unsigned g_gen = 0;
__device__ unsigned g_arrive = 0;

// ---------------- software grid barrier (all NBLK blocks resident) -------------
__device__ __forceinline__ void grid_bar()
{
    __syncthreads();
    if (threadIdx.x == 0) {
        __threadfence();
        unsigned gen = *(volatile unsigned*)&g_gen;
        if (atomicAdd(&g_arrive, 1u) == NBLK - 1) {
            g_arrive = 0;
            __threadfence();
            atomicAdd(&g_gen, 1u);
        } else {
            while (*(volatile unsigned*)&g_gen == gen) {}
        }
        __threadfence();
    }
    __syncthreads();
}

// =================== persistent mega-kernel ====================================
// stage0: blocks 0-2 idx build, blocks 3-147 conv+pos (parallel) | bar
// then per dilation: qkv | bar | flash(+proj/resid/scatter) | bar
__global__ void __launch_bounds__(512) fused_all_kernel(
    const float* __restrict__ x,
    const float* __restrict__ Wc,    // [64][64] patch conv
    const float* __restrict__ bc,
    const float* __restrict__ pos,   // [64][32768]
    const float* __restrict__ qkvw0, const float* __restrict__ qkvb0,
    const float* __restrict__ pw0,   const float* __restrict__ pb0,
    const float* __restrict__ qkvw1, const float* __restrict__ qkvb1,
    const float* __restrict__ pw1,   const float* __restrict__ pb1,
    const float* __restrict__ qkvw2, const float* __restrict__ qkvb2,
    const float* __restrict__ pw2,   const float* __restrict__ pb2)
{
    extern __shared__ float DSM[];
    int tid = threadIdx.x;
    int bid = blockIdx.x;

    // ---------------- stage 0a: idx build (blocks 0..2, ss-table) --------------
    if (bid < 3) {
        unsigned char* valid = (unsigned char*)DSM;          // 769 B
        int* scan = (int*)(DSM + 256);                       // 512 ints
        int dil = (bid == 0) ? 2 : (bid == 1) ? 4 : 6;
        int* out = g_idx3 + bid * NTOK;
        float fd = (float)dil;

        for (int ss = tid; ss < 769; ss += 512) {
            float d = sqrtf((float)ss);
            valid[ss] = ((fmodf(d, fd) == 0.0f) || (ss == 0)) ? 1 : 0;
        }
        __syncthreads();

        int base = tid * 64;
        unsigned long long fl = 0ull;
        int ccnt = 0;
        for (int j = 0; j < 64; ++j) {
            int n = base + j;
            int zz = (n >> 10) - 16, yy = ((n >> 5) & 31) - 16, xx = (n & 31) - 16;
            int ss = zz*zz + yy*yy + xx*xx;
            if (valid[ss]) { fl |= (1ull << j); ccnt++; }
        }
        scan[tid] = ccnt;
        __syncthreads();
        for (int off = 1; off < 512; off <<= 1) {
            int v = (tid >= off) ? scan[tid - off] : 0;
            __syncthreads();
            scan[tid] += v;
            __syncthreads();
        }
        int pos2 = scan[tid] - ccnt;
        for (int j = 0; j < 64; ++j)
            if (fl & (1ull << j)) out[pos2++] = base + j;
        if (tid == 511) g_M3[bid] = scan[511];
    }
    // ---------------- stage 0b: conv + pos (blocks 3..147) ---------------------
    else {
        float* S = DSM;                       // Praw 64x128 then O 128x68
        for (int ti = bid - 3; ti < 256; ti += NBLK - 3) {
            int z  = ti >> 3, yq = ti & 7;
            int n0 = ti * 128;                // 128 contiguous tokens

            __syncthreads();                  // S reuse across ti
            #pragma unroll
            for (int j = 0; j < 4; ++j) {
                int e  = tid + 512 * j;       // 2048 float4
                int r  = e >> 5;              // 0..63: dz=r>>4, yloc=r&15
                int c4 = e & 31;
                const float4* src = (const float4*)(x
                    + (size_t)(4*z + (r >> 4)) * 16384
                    + (16*yq + (r & 15)) * 128 + c4 * 4);
                *(float4*)&S[r * 128 + c4 * 4] = *src;
            }
            __syncthreads();

            int ch = tid & 63;
            int tg = (tid >> 6) & 3;          // y row 0..3
            int hf = tid >> 8;                // token half
            float w[64];
            {
                const float4* wp = (const float4*)(Wc + ch * 64);
                #pragma unroll
                for (int i = 0; i < 16; ++i) {
                    float4 t4 = wp[i];
                    w[4*i] = t4.x; w[4*i+1] = t4.y;
                    w[4*i+2] = t4.z; w[4*i+3] = t4.w;
                }
            }
            float bv = bc[ch];
            float acc[16];
            #pragma unroll
            for (int i = 0; i < 16; ++i) acc[i] = bv;

            #pragma unroll
            for (int k4 = 0; k4 < 16; ++k4) {     // k4 = dz*4+dy
                int row = (k4 >> 2) * 16 + tg * 4 + (k4 & 3);
                const float4* Pr = (const float4*)&S[row * 128];
                float wx = w[4*k4], wy = w[4*k4+1];
                float wz = w[4*k4+2], ww = w[4*k4+3];
                #pragma unroll
                for (int i = 0; i < 16; ++i) {
                    float4 p = Pr[hf * 16 + i];
                    acc[i] += p.x * wx;
                    acc[i] += p.y * wy;
                    acc[i] += p.z * wz;
                    acc[i] += p.w * ww;
                }
            }
            __syncthreads();                      // Praw dead

            #pragma unroll
            for (int i = 0; i < 16; ++i)
                S[(tg * 32 + hf * 16 + i) * 68 + ch] = acc[i];
            __syncthreads();

            // pos add + g_hT write (coalesced per channel)
            #pragma unroll
            for (int rep = 0; rep < 16; ++rep) {
                int e  = tid + 512 * rep;         // 8192 elems
                int cc = e >> 7, t = e & 127;
                float v = S[t * 68 + cc] + pos[cc * NTOK + n0 + t];
                S[t * 68 + cc] = v;
                g_hT[cc * NTOK + n0 + t] = v;
            }
            __syncthreads();

            #pragma unroll
            for (int j = 0; j < 4; ++j) {
                int e  = tid + 512 * j;           // 2048 float4
                int t  = e >> 4, c4 = e & 15;
                float4 v = *(const float4*)&S[t * 68 + c4 * 4];
                *(float4*)&g_t[(size_t)(n0 + t) * 64 + c4 * 4] = v;
            }
        }
    }
    grid_bar();

    const float* QW[3] = {qkvw0, qkvw1, qkvw2};
    const float* QB[3] = {qkvb0, qkvb1, qkvb2};
    const float* PW[3] = {pw0, pw1, pw2};
    const float* PB[3] = {pb0, pb1, pb2};

    for (int di = 0; di < 3; ++di) {
        int M = g_M3[di];
        const int* __restrict__ idx = g_idx3 + di * NTOK;
        int mtiles = (M + 31) >> 5;

        // ---------------- stage: QKV (scale 1/8 folded into Q) -----------------
        {
            float (*Ts)[68] = (float(*)[68])DSM;
            const float* W  = QW[di];
            const float* bb = QB[di];

            int oc   = tid >> 1;          // 0..255 (valid < 192)
            int half = tid & 1;
            float w[64]; float bv = 0.f;
            if (oc < 192) {
                const float4* wr = (const float4*)(W + oc * 64);
                #pragma unroll
                for (int i = 0; i < 16; ++i) {
                    float4 t4 = wr[i];
                    w[4*i] = t4.x; w[4*i+1] = t4.y;
                    w[4*i+2] = t4.z; w[4*i+3] = t4.w;
                }
                bv = bb[oc];
            }

            for (int mt = bid; mt < mtiles; mt += NBLK) {
                int m0 = mt * 32;
                __syncthreads();
                #pragma unroll
                for (int j = 0; j < 4; ++j) {
                    int e = tid + 512 * j;
                    int ml = e >> 6, k = e & 63;
                    int m = m0 + ml;
                    Ts[ml][k] = (m < M) ? g_t[idx[m] * 64 + k] : 0.f;
                }
                __syncthreads();
                if (oc < 192) {
                    int mmax = min(32, M - m0);
                    #pragma unroll
                    for (int g = 0; g < 2; ++g) {
                        int ml0 = half * 16 + g * 8;
                        float acc[8];
                        #pragma unroll
                        for (int u = 0; u < 8; ++u) acc[u] = bv;
                        #pragma unroll
                        for (int k4 = 0; k4 < 16; ++k4) {
                            #pragma unroll
                            for (int u = 0; u < 8; ++u) {
                                float4 t4 = *(const float4*)&Ts[ml0 + u][k4 * 4];
                                acc[u] += t4.x * w[4*k4];
                                acc[u] += t4.y * w[4*k4+1];
                                acc[u] += t4.z * w[4*k4+2];
                                acc[u] += t4.w * w[4*k4+3];
                            }
                        }
                        #pragma unroll
                        for (int u = 0; u < 8; ++u) {
                            int ml = ml0 + u;
                            if (ml < mmax) {
                                int m = m0 + ml;
                                if      (oc <  64) g_qs[m * 64 + oc]       = acc[u] * 0.125f;
                                else if (oc < 128) g_ks[m * 64 + oc - 64]  = acc[u];
                                else               g_vs[m * 64 + oc - 128] = acc[u];
                            }
                        }
                    }
                }
            }
        }
        grid_bar();

        // ------ stage: flash attn (double-buffered K/V) + proj + scatter -------
        {
            float (*K0)[68]  = (float(*)[68])DSM;
            float (*V0)[68]  = (float(*)[68])(DSM + 64 * 68);
            float (*K1)[68]  = (float(*)[68])(DSM + 128 * 68);
            float (*V1)[68]  = (float(*)[68])(DSM + 192 * 68);
            float (*Psm)[68] = (float(*)[68])(DSM + 256 * 68);
            float (*Ysm)[68] = (float(*)[68])(DSM + 288 * 68);

            int r  = tid >> 4;        // query row 0..31
            int qq = tid & 15;
            int cb = qq * 4;
            int nl_me = tid >> 4;     // for loads: e=tid -> nl=tid>>4, k4=tid&15
            int k4_me = tid & 15;

            for (int mt = bid; mt < mtiles; mt += NBLK) {
                int  m0    = mt * 32;
                int  m     = m0 + r;
                bool validq = (m < M);

                float qreg[64];
                {
                    const float4* qp = (const float4*)(g_qs + (size_t)(validq ? m : m0) * 64);
                    #pragma unroll
                    for (int i = 0; i < 16; ++i) {
                        float4 v = qp[i];
                        qreg[4*i] = v.x; qreg[4*i+1] = v.y;
                        qreg[4*i+2] = v.z; qreg[4*i+3] = v.w;
                    }
                }
                float y[4] = {0.f, 0.f, 0.f, 0.f};
                float row_max = -1e30f, row_sum = 0.f;

                int nt = (M + 63) >> 6;
                float4 kst[2], vst[2];

                // preload tile 0 into buf 0
                __syncthreads();                      // DSM reuse guard
                #pragma unroll
                for (int j = 0; j < 2; ++j) {
                    int nl = nl_me + 32 * j;
                    int n  = nl;                      // tile 0
                    kst[j] = make_float4(0.f,0.f,0.f,0.f);
                    vst[j] = kst[j];
                    if (n < M) {
                        kst[j] = *(const float4*)(g_ks + n * 64 + k4_me * 4);
                        vst[j] = *(const float4*)(g_vs + n * 64 + k4_me * 4);
                    }
                    *(float4*)&K0[nl][k4_me * 4] = kst[j];
                    *(float4*)&V0[nl][k4_me * 4] = vst[j];
                }
                __syncthreads();

                for (int t = 0; t < nt; ++t) {
                    float (*Kc)[68] = (t & 1) ? K1 : K0;
                    float (*Vc)[68] = (t & 1) ? V1 : V0;
                    bool more = (t + 1 < nt);

                    // issue loads for next tile (latency hidden by compute)
                    if (more) {
                        #pragma unroll
                        for (int j = 0; j < 2; ++j) {
                            int nl = nl_me + 32 * j;
                            int n  = (t + 1) * 64 + nl;
                            kst[j] = make_float4(0.f,0.f,0.f,0.f);
                            vst[j] = kst[j];
                            if (n < M) {
                                kst[j] = *(const float4*)(g_ks + n * 64 + k4_me * 4);
                                vst[j] = *(const float4*)(g_vs + n * 64 + k4_me * 4);
                            }
                        }
                    }

                    int n0 = t * 64;
                    float sc[4];
                    float tmax = -1e30f;
                    #pragma unroll
                    for (int kk = 0; kk < 4; ++kk) {
                        int nl = qq + 16 * kk;
                        float acc = 0.f;
                        #pragma unroll
                        for (int k4 = 0; k4 < 16; ++k4) {
                            float4 kvec = *(const float4*)&Kc[nl][k4 * 4];
                            acc += qreg[4*k4]   * kvec.x;
                            acc += qreg[4*k4+1] * kvec.y;
                            acc += qreg[4*k4+2] * kvec.z;
                            acc += qreg[4*k4+3] * kvec.w;
                        }
                        if (n0 + nl >= M) acc = -1e30f;
                        sc[kk] = acc;
                        tmax = fmaxf(tmax, acc);
                    }
                    #pragma unroll
                    for (int o = 1; o < 16; o <<= 1)
                        tmax = fmaxf(tmax, __shfl_xor_sync(0xffffffffu, tmax, o));

                    float nmax = fmaxf(row_max, tmax);
                    float corr = __expf(row_max - nmax);
                    float lsum = 0.f;
                    #pragma unroll
                    for (int kk = 0; kk < 4; ++kk) {
                        float p = __expf(sc[kk] - nmax);
                        Psm[r][qq + 16 * kk] = p;
                        lsum += p;
                    }
                    #pragma unroll
                    for (int o = 1; o < 16; o <<= 1)
                        lsum += __shfl_xor_sync(0xffffffffu, lsum, o);
                    row_sum = row_sum * corr + lsum;
                    row_max = nmax;
                    y[0] *= corr; y[1] *= corr; y[2] *= corr; y[3] *= corr;
                    __syncwarp();

                    #pragma unroll 4
                    for (int nl = 0; nl < 64; ++nl) {
                        float p = Psm[r][nl];
                        float4 v0 = *(const float4*)&Vc[nl][cb];
                        y[0] += p * v0.x; y[1] += p * v0.y;
                        y[2] += p * v0.z; y[3] += p * v0.w;
                    }

                    // store next tile into the other buffer
                    if (more) {
                        float (*Kn)[68] = (t & 1) ? K0 : K1;
                        float (*Vn)[68] = (t & 1) ? V0 : V1;
                        #pragma unroll
                        for (int j = 0; j < 2; ++j) {
                            int nl = nl_me + 32 * j;
                            *(float4*)&Kn[nl][k4_me * 4] = kst[j];
                            *(float4*)&Vn[nl][k4_me * 4] = vst[j];
                        }
                    }
                    __syncthreads();
                }

                float inv = 1.0f / row_sum;
                if (validq)
                    *(float4*)&Ysm[r][cb] =
                        make_float4(y[0]*inv, y[1]*inv, y[2]*inv, y[3]*inv);
                __syncthreads();

                // proj + residual + dual scatter
                int oc = tid & 63;
                int rb = tid >> 6;        // 0..7
                float wrow[64];
                {
                    const float4* wr = (const float4*)(PW[di] + oc * 64);
                    #pragma unroll
                    for (int i = 0; i < 16; ++i) {
                        float4 v = wr[i];
                        wrow[4*i] = v.x; wrow[4*i+1] = v.y;
                        wrow[4*i+2] = v.z; wrow[4*i+3] = v.w;
                    }
                }
                float bv = PB[di][oc];
                int mmax = min(32, M - m0);
                for (int rr = rb; rr < mmax; rr += 8) {
                    float a0 = bv;
                    #pragma unroll
                    for (int k4 = 0; k4 < 16; ++k4) {
                        float4 y0 = *(const float4*)&Ysm[rr][k4 * 4];
                        a0 += y0.x * wrow[4*k4];
                        a0 += y0.y * wrow[4*k4+1];
                        a0 += y0.z * wrow[4*k4+2];
                        a0 += y0.w * wrow[4*k4+3];
                    }
                    a0 += Ysm[rr][oc];
                    int tok = idx[m0 + rr];
                    g_t [tok * 64 + oc]   = a0;
                    g_hT[oc * NTOK + tok] = a0;
                }
                __syncthreads();
            }
        }
        if (di < 2) grid_bar();
    }
}

// ---------------- trilinear x4 upsample: hT[c][32^3] -> out[c][128^3] ----------
__global__ void __launch_bounds__(256) upsample_kernel(float* __restrict__ out)
{
    const float S = 31.0f / 127.0f;
    int zo  = blockIdx.x;
    int c   = blockIdx.y;
    int tid = threadIdx.x;

    float pz = (float)zo * S;
    int z0 = (int)pz;
    int z1 = min(z0 + 1, 31);
    float wz = pz - (float)z0;

    __shared__ float F[1024];
    __shared__ float R[128][33];

    const float* p0 = g_hT + c * NTOK + z0 * 1024;
    const float* p1 = g_hT + c * NTOK + z1 * 1024;
    #pragma unroll
    for (int j = 0; j < 4; ++j) {
        int i = tid + 256 * j;
        float a = p0[i];
        F[i] = a + wz * (p1[i] - a);
    }
    __syncthreads();

    int w = tid >> 5, lane = tid & 31;

    #pragma unroll
    for (int j = 0; j < 16; ++j) {
        int yo = j * 8 + w;
        float py = (float)yo * S;
        int y0 = (int)py;
        int y1 = min(y0 + 1, 31);
        float wy = py - (float)y0;
        float a = F[y0 * 32 + lane];
        float b = F[y1 * 32 + lane];
        R[yo][lane] = a + wy * (b - a);
    }
    __syncthreads();

    int   x0[4], x1[4];
    float wx[4];
    #pragma unroll
    for (int j = 0; j < 4; ++j) {
        int xo = lane * 4 + j;
        float px = (float)xo * S;
        x0[j] = (int)px;
        x1[j] = min(x0[j] + 1, 31);
        wx[j] = px - (float)x0[j];
    }

    size_t obase = ((size_t)(c * 128 + zo)) * 16384;
    #pragma unroll
    for (int it = 0; it < 16; ++it) {
        int yo = it * 8 + w;
        const float* Rr = &R[yo][0];
        float4 o;
        #pragma unroll
        for (int j = 0; j < 4; ++j) {
            float r0 = Rr[x0[j]];
            (&o.x)[j] = r0 + wx[j] * (Rr[x1[j]] - r0);
        }
        __stcs((float4*)(out + obase + (size_t)yo * 128 + lane * 4), o);
    }
}

// ---------------- launch --------------------------------------------------------
extern "C" void kernel_launch(void* const* d_in, const int* in_sizes, int n_in,
                              void* d_out, int out_size)
{
    cudaFuncSetAttribute(fused_all_kernel,
                         cudaFuncAttributeMaxDynamicSharedMemorySize, SMEM_BYTES);

    fused_all_kernel<<<NBLK, 512, SMEM_BYTES>>>(
        (const float*)d_in[0],  (const float*)d_in[1],
        (const float*)d_in[2],  (const float*)d_in[3],
        (const float*)d_in[4],  (const float*)d_in[5],
        (const float*)d_in[6],  (const float*)d_in[7],
        (const float*)d_in[8],  (const float*)d_in[9],
        (const float*)d_in[10], (const float*)d_in[11],
        (const float*)d_in[12], (const float*)d_in[13],
        (const float*)d_in[14], (const float*)d_in[15]);

    upsample_kernel<<<dim3(128, 64), 256>>>((float*)d_out);
}